// round 16
// baseline (speedup 1.0000x reference)
#include <cuda_runtime.h>
#include <cstdint>

// Problem constants: B=2, S=2048, D=1024, H=16, HD=64
#define BB 2
#define SS 2048
#define DD 1024
#define HH 16
#define HDD 64
#define MROWS (BB * SS)   // 4096

__device__ float g_Q[BB * SS * DD];
__device__ float g_K[BB * SS * DD];
__device__ float g_V[BB * SS * DD];   // holds Vt: [b][h][d][token]
__device__ float g_C[BB * SS * DD];
// tf32-pre-rounded inputs
__device__ float g_Xr[MROWS * DD];
__device__ float g_Wqr[DD * DD];
__device__ float g_Wkr[DD * DD];
__device__ float g_Wvr[DD * DD];
__device__ float g_Wor[DD * DD];

// ---------------------------------------------------------------------------
// tf32 / cp.async helpers
// ---------------------------------------------------------------------------
__device__ __forceinline__ uint32_t f2tf32(float x) {
    uint32_t u;
    asm("cvt.rna.tf32.f32 %0, %1;" : "=r"(u) : "f"(x));
    return u;
}
__device__ __forceinline__ float tf32f(float x) {
    return __uint_as_float(f2tf32(x));
}
__device__ __forceinline__ void cp16(uint32_t dst, const void* src) {
    asm volatile("cp.async.cg.shared.global [%0], [%1], 16;"
                 :: "r"(dst), "l"(src));
}

#define MMA_TF32(d, a, b)                                                    \
    asm volatile(                                                            \
        "mma.sync.aligned.m16n8k8.row.col.f32.tf32.tf32.f32 "                \
        "{%0,%1,%2,%3}, {%4,%5,%6,%7}, {%8,%9}, {%0,%1,%2,%3};"              \
        : "+f"((d)[0]), "+f"((d)[1]), "+f"((d)[2]), "+f"((d)[3])             \
        : "r"((a)[0]), "r"((a)[1]), "r"((a)[2]), "r"((a)[3]),                \
          "r"((b)[0]), "r"((b)[1]))

// ---------------------------------------------------------------------------
// Pre-round to tf32 (RNA), float4-vectorized.
// ---------------------------------------------------------------------------
__global__ __launch_bounds__(256)
void round_tf32_kernel(const float* __restrict__ src, float* __restrict__ dst,
                       int n4)
{
    const int i = blockIdx.x * blockDim.x + threadIdx.x;
    if (i < n4) {
        float4 v = ((const float4*)src)[i];
        v.x = tf32f(v.x); v.y = tf32f(v.y);
        v.z = tf32f(v.z); v.w = tf32f(v.w);
        ((float4*)dst)[i] = v;
    }
}

// ---------------------------------------------------------------------------
// tf32 tensor-core GEMM (round 15 core): 4-stage cp.async pipeline,
// pre-rounded inputs, k-slot-paired fragments.
// OUTMODE: 0 = plain fp32 out; 1 = tf32-rounded out (K);
//          2 = tf32-rounded TRANSPOSED out (V -> Vt[b][h][d][token]).
// ---------------------------------------------------------------------------
#define GSM_BYTES 81920
#define G_ASTG 3072     // floats per A stage (128*24)
#define G_BSTG 2048     // floats per B stage (16*128)
#define G_BOFF 12288    // float offset of B stages (4*3072)

template <int OUTMODE>
__global__ __launch_bounds__(256, 2)
void gemm_tf32(const float* __restrict__ A, const float* __restrict__ W,
               const float* __restrict__ bias, float* __restrict__ C)
{
    constexpr int K = 1024, N = 1024;
    extern __shared__ float gsm[];

    const int tid  = threadIdx.x;
    const int lane = tid & 31;
    const int li   = lane >> 2;           // 0..7
    const int lj   = lane & 3;            // 0..3
    const int wid  = tid >> 5;
    const int warp_m = wid >> 2;          // 0..1
    const int warp_n = wid & 3;           // 0..3
    const int rowBase = blockIdx.y * 128;
    const int colBase = blockIdx.x * 128;

    const uint32_t smem_u32 = (uint32_t)__cvta_generic_to_shared(gsm);

    const int ar  = tid >> 1;
    const int ac  = (tid & 1) * 2;
    const int br  = tid >> 4;
    const int bc0 = (tid & 15) * 2;
    const float* Asrc = A + (size_t)(rowBase + ar) * K + ac * 4;
    const float* Bsrc = W + (size_t)br * N + colBase + bc0 * 4;
    const uint32_t a_dst = smem_u32 + ar * 96 + ac * 16;         // stride 24 fl
    const uint32_t bsw   = (uint32_t)(br & 7);                   // chunk swz
    const uint32_t b_dst = smem_u32 + G_BOFF * 4 + br * 512;
    const uint32_t bo0 = ((uint32_t)bc0 ^ bsw) << 4;
    const uint32_t bo1 = ((uint32_t)(bc0 + 1) ^ bsw) << 4;

#define G_ISSUE(t)                                                           \
    do {                                                                     \
        const int s_ = (t) & 3;                                              \
        const uint32_t ab_ = a_dst + s_ * (G_ASTG * 4);                      \
        const float* as_ = Asrc + (t) * 16;                                  \
        cp16(ab_, as_);                                                      \
        cp16(ab_ + 16, as_ + 4);                                             \
        const uint32_t bb_ = b_dst + s_ * (G_BSTG * 4);                      \
        const float* bs_ = Bsrc + (size_t)(t) * 16 * N;                      \
        cp16(bb_ + bo0, bs_);                                                \
        cp16(bb_ + bo1, bs_ + 4);                                            \
        asm volatile("cp.async.commit_group;");                              \
    } while (0)

    G_ISSUE(0);
    G_ISSUE(1);
    G_ISSUE(2);

    float acc[4][4][4];
#pragma unroll
    for (int mt = 0; mt < 4; mt++)
#pragma unroll
        for (int nt = 0; nt < 4; nt++)
#pragma unroll
            for (int r = 0; r < 4; r++) acc[mt][nt][r] = 0.f;

    const int chv = warp_n * 8 + (li >> 2);
    const int wi  = li & 3;
    const int e0  = 2 * lj;
    const int e1  = 2 * lj + 1;

    const int niter = K / 16;   // 64
    for (int kt = 0; kt < niter; kt++) {
        if (kt < niter - 2)      asm volatile("cp.async.wait_group 2;");
        else if (kt == niter - 2) asm volatile("cp.async.wait_group 1;");
        else                      asm volatile("cp.async.wait_group 0;");
        __syncthreads();
        if (kt + 3 < niter) G_ISSUE(kt + 3);

        const float* Ast = gsm + (kt & 3) * G_ASTG;
        const float* Bst = gsm + G_BOFF + (kt & 3) * G_BSTG;

#pragma unroll
        for (int s = 0; s < 2; s++) {
            const int k0 = s * 8 + e0;
            uint32_t af[4][4];
            uint32_t bf[4][2];
#pragma unroll
            for (int mt = 0; mt < 4; mt++) {
                const int r0 = (warp_m * 64 + mt * 16 + li) * 24;
                const float2 alo = *(const float2*)&Ast[r0 + k0];
                const float2 ahi = *(const float2*)&Ast[r0 + 192 + k0];
                af[mt][0] = __float_as_uint(alo.x);
                af[mt][1] = __float_as_uint(ahi.x);
                af[mt][2] = __float_as_uint(alo.y);
                af[mt][3] = __float_as_uint(ahi.y);
            }
            const int rb0 = k0 * 128;
#pragma unroll
            for (int nt = 0; nt < 4; nt++) {
                const int ch = chv + nt * 2;
                bf[nt][0] = __float_as_uint(Bst[rb0 + ((ch ^ e0) << 2) + wi]);
                bf[nt][1] = __float_as_uint(
                    Bst[rb0 + 128 + ((ch ^ e1) << 2) + wi]);
            }
#pragma unroll
            for (int mt = 0; mt < 4; mt++)
#pragma unroll
                for (int nt = 0; nt < 4; nt++)
                    MMA_TF32(acc[mt][nt], af[mt], bf[nt]);
        }
    }

    // ---- epilogue ----
#pragma unroll
    for (int mt = 0; mt < 4; mt++) {
        const int r = rowBase + warp_m * 64 + mt * 16 + li;
#pragma unroll
        for (int nt = 0; nt < 4; nt++) {
            const int c = colBase + warp_n * 32 + nt * 8 + lj * 2;
            const float bi0 = bias[c], bi1 = bias[c + 1];
            float o00 = acc[mt][nt][0] + bi0, o01 = acc[mt][nt][1] + bi1;
            float o10 = acc[mt][nt][2] + bi0, o11 = acc[mt][nt][3] + bi1;
            if (OUTMODE == 0) {
                *(float2*)&C[(size_t)r * N + c]       = make_float2(o00, o01);
                *(float2*)&C[(size_t)(r + 8) * N + c] = make_float2(o10, o11);
            } else if (OUTMODE == 1) {
                *(float2*)&C[(size_t)r * N + c] =
                    make_float2(tf32f(o00), tf32f(o01));
                *(float2*)&C[(size_t)(r + 8) * N + c] =
                    make_float2(tf32f(o10), tf32f(o11));
            } else {
                // transposed: Vt[b][h][d][token]; r,r+8 share b; c,c+1 share h
                const int b_  = r >> 11;
                const int tok = r & (SS - 1);
                const int h_  = c >> 6;
                const int d_  = c & 63;
                float* base = C + ((size_t)(b_ * HH + h_) * HDD) * SS;
                base[(size_t)d_ * SS + tok]           = tf32f(o00);
                base[(size_t)(d_ + 1) * SS + tok]     = tf32f(o01);
                base[(size_t)d_ * SS + tok + 8]       = tf32f(o10);
                base[(size_t)(d_ + 1) * SS + tok + 8] = tf32f(o11);
            }
        }
    }
}

// ---------------------------------------------------------------------------
// Tensor-core flash attention (tf32), register-resident P, transposed V.
// CTA = (b, h, 128-q tile), 256 threads = 8 warps; warp w owns q rows
// [16w, 16w+16). 16 key-tiles of 128 over S=2048; triple-buffered K/V.
//
// K smem: [128 keys][72 floats]  -> score B-frags LDS.64 (adjacent d-pair)
// V smem: [64 d][132 floats]     -> PV B-frags LDS.64 (adjacent key-pair,
//         from Vt[b][h][d][token]); stride 132: banks 4li+2lj all distinct.
// P stays in registers (C->A identity). 1 barrier per tile.
// smem total: 3*9216 + 3*8448 floats = 211,968 B.
// ---------------------------------------------------------------------------
#define KST 72                        // K row stride (floats)
#define VTS 132                       // Vt row stride (floats)
#define KSTG (128 * KST)              // 9216 floats per K stage
#define VSTG (64 * VTS)               // 8448 floats per V stage
#define VOFF (3 * KSTG)               // 27648 float offset of V stages
#define ATT_SMEM_BYTES ((3 * KSTG + 3 * VSTG) * 4)   // 211,968

#define QSCALE (0.125f * 1.44269504088896f)   // 1/sqrt(64) * log2(e)

__global__ __launch_bounds__(256, 1)
void attn_tc()
{
    extern __shared__ float sm[];

    const int tid  = threadIdx.x;
    const int lane = tid & 31;
    const int w    = tid >> 5;                // 0..7
    const int li   = lane >> 2;               // 0..7
    const int lj   = lane & 3;                // 0..3
    const int b = blockIdx.z, h = blockIdx.y;
    const int q0 = blockIdx.x * 128;

    const float* Qg  = g_Q + ((size_t)b * SS + q0) * DD + h * HDD;
    const float* Kg  = g_K + (size_t)b * SS * DD + h * HDD;
    const float* Vtg = g_V + ((size_t)(b * HH + h) * HDD) * SS;  // [d][token]

    const uint32_t smem_u32 = (uint32_t)__cvta_generic_to_shared(sm);

    // K cp.async mapping: thread -> key row tid>>1, chunks [ihalf, ihalf+8)
    const int irow  = tid >> 1;               // 0..127
    const int ihalf = (tid & 1) * 8;          // 0 or 8
    const float* ksrc_base = Kg + (size_t)irow * DD + ihalf * 4;
    const uint32_t krow_dst = smem_u32 + irow * (KST * 4) + ihalf * 16;
    // V cp.async mapping: thread -> d row tid>>2, 8 chunks of 4 tokens
    const int vd    = tid >> 2;               // 0..63
    const int vch0  = (tid & 3) * 8;          // chunk base (of 32 chunks)
    const float* vsrc_base = Vtg + (size_t)vd * SS + vch0 * 4;
    const uint32_t vrow_dst = smem_u32 + VOFF * 4 + vd * (VTS * 4) + vch0 * 16;

#define AKV_ISSUE(t)                                                         \
    do {                                                                     \
        const int st_ = (t) % 3;                                             \
        const uint32_t kd_ = krow_dst + (uint32_t)st_ * (KSTG * 4);          \
        const uint32_t vd_ = vrow_dst + (uint32_t)st_ * (VSTG * 4);          \
        const float* ks_ = ksrc_base + (size_t)(t) * 128 * DD;               \
        const float* vs_ = vsrc_base + (t) * 128;                            \
        _Pragma("unroll")                                                    \
        for (int q_ = 0; q_ < 8; q_++) {                                     \
            cp16(kd_ + q_ * 16, ks_ + q_ * 4);                               \
            cp16(vd_ + q_ * 16, vs_ + q_ * 4);                               \
        }                                                                    \
        asm volatile("cp.async.commit_group;");                              \
    } while (0)

    AKV_ISSUE(0);
    AKV_ISSUE(1);

    // ---- Q A-fragments from gmem (k-slot pairing), scaled, tf32 ----
    const int r  = w * 16 + li;               // q rows r, r+8
    const int kc = 2 * lj;
    uint32_t qf[8][4];
#pragma unroll
    for (int s = 0; s < 8; s++) {
        const float2 lo = *(const float2*)(Qg + (size_t)r * DD + s * 8 + kc);
        const float2 hi = *(const float2*)(Qg + (size_t)(r + 8) * DD + s * 8 + kc);
        qf[s][0] = f2tf32(lo.x * QSCALE);
        qf[s][1] = f2tf32(hi.x * QSCALE);
        qf[s][2] = f2tf32(lo.y * QSCALE);
        qf[s][3] = f2tf32(hi.y * QSCALE);
    }

    float m0 = -1e30f, m1 = -1e30f, l0 = 0.f, l1 = 0.f;
    float oacc[8][4];
#pragma unroll
    for (int nt = 0; nt < 8; nt++)
#pragma unroll
        for (int i = 0; i < 4; i++) oacc[nt][i] = 0.f;

    float sacc[16][4];

    for (int kt = 0; kt < 16; kt++) {
        if (kt < 15) asm volatile("cp.async.wait_group 1;");
        else         asm volatile("cp.async.wait_group 0;");
        __syncthreads();
        if (kt + 2 < 16) AKV_ISSUE(kt + 2);

        const float* Kb = sm + (kt % 3) * KSTG;
        const float* Vb = sm + VOFF + (kt % 3) * VSTG;

        // ---- scores (log2-domain): K B-frags LDS.64 ----
#pragma unroll
        for (int nt = 0; nt < 16; nt++)
#pragma unroll
            for (int i = 0; i < 4; i++) sacc[nt][i] = 0.f;
#pragma unroll
        for (int s = 0; s < 8; s++) {
            const int cofs = s * 8 + kc;
#pragma unroll
            for (int nt = 0; nt < 16; nt++) {
                const float2 kv =
                    *(const float2*)&Kb[(nt * 8 + li) * KST + cofs];
                uint32_t bf[2] = {__float_as_uint(kv.x), __float_as_uint(kv.y)};
                MMA_TF32(sacc[nt], qf[s], bf);
            }
        }

        // ---- online softmax in registers ----
        {
            float tma0 = -1e30f, tmb0 = -1e30f, tma1 = -1e30f, tmb1 = -1e30f;
#pragma unroll
            for (int nt = 0; nt < 16; nt += 2) {
                tma0 = fmaxf(tma0, fmaxf(sacc[nt][0], sacc[nt][1]));
                tmb0 = fmaxf(tmb0, fmaxf(sacc[nt + 1][0], sacc[nt + 1][1]));
                tma1 = fmaxf(tma1, fmaxf(sacc[nt][2], sacc[nt][3]));
                tmb1 = fmaxf(tmb1, fmaxf(sacc[nt + 1][2], sacc[nt + 1][3]));
            }
            float tm0 = fmaxf(tma0, tmb0);
            float tm1 = fmaxf(tma1, tmb1);
            tm0 = fmaxf(tm0, __shfl_xor_sync(0xffffffffu, tm0, 1));
            tm0 = fmaxf(tm0, __shfl_xor_sync(0xffffffffu, tm0, 2));
            tm1 = fmaxf(tm1, __shfl_xor_sync(0xffffffffu, tm1, 1));
            tm1 = fmaxf(tm1, __shfl_xor_sync(0xffffffffu, tm1, 2));

            const float nm0 = fmaxf(m0, tm0);
            const float nm1 = fmaxf(m1, tm1);
            const float cr0 = exp2f(m0 - nm0);
            const float cr1 = exp2f(m1 - nm1);

            float sa0 = 0.f, sb0 = 0.f, sa1 = 0.f, sb1 = 0.f;
#pragma unroll
            for (int nt = 0; nt < 16; nt++) {
                const float p00 = exp2f(sacc[nt][0] - nm0);
                const float p01 = exp2f(sacc[nt][1] - nm0);
                const float p10 = exp2f(sacc[nt][2] - nm1);
                const float p11 = exp2f(sacc[nt][3] - nm1);
                sa0 += p00; sb0 += p01;
                sa1 += p10; sb1 += p11;
                sacc[nt][0] = tf32f(p00);
                sacc[nt][1] = tf32f(p01);
                sacc[nt][2] = tf32f(p10);
                sacc[nt][3] = tf32f(p11);
            }
            float ss0 = sa0 + sb0, ss1 = sa1 + sb1;
            ss0 += __shfl_xor_sync(0xffffffffu, ss0, 1);
            ss0 += __shfl_xor_sync(0xffffffffu, ss0, 2);
            ss1 += __shfl_xor_sync(0xffffffffu, ss1, 1);
            ss1 += __shfl_xor_sync(0xffffffffu, ss1, 2);

            l0 = l0 * cr0 + ss0;
            l1 = l1 * cr1 + ss1;
            m0 = nm0;
            m1 = nm1;

#pragma unroll
            for (int nt = 0; nt < 8; nt++) {
                oacc[nt][0] *= cr0; oacc[nt][1] *= cr0;
                oacc[nt][2] *= cr1; oacc[nt][3] *= cr1;
            }
        }

        // ---- PV: P A-frag = sacc (C->A identity); V B-frags LDS.64 from
        // Vt[d][key]: keys (s2*8+2lj, +1) adjacent; d = nt*8+li ----
#pragma unroll
        for (int s2 = 0; s2 < 16; s2++) {
            uint32_t pf[4];
            pf[0] = __float_as_uint(sacc[s2][0]);
            pf[1] = __float_as_uint(sacc[s2][2]);
            pf[2] = __float_as_uint(sacc[s2][1]);
            pf[3] = __float_as_uint(sacc[s2][3]);
            const int kb = s2 * 8 + kc;
#pragma unroll
            for (int nt = 0; nt < 8; nt++) {
                const float2 vv =
                    *(const float2*)&Vb[(nt * 8 + li) * VTS + kb];
                uint32_t bf[2] = {__float_as_uint(vv.x), __float_as_uint(vv.y)};
                MMA_TF32(oacc[nt], pf, bf);
            }
        }
    }

    // ---- finalize: /l, write ctx (tf32-rounded for the Wo GEMM) ----
    const float inv0 = 1.f / l0;
    const float inv1 = 1.f / l1;
    float* Cg0 = g_C + ((size_t)b * SS + q0 + r) * DD + h * HDD;
    float* Cg1 = g_C + ((size_t)b * SS + q0 + r + 8) * DD + h * HDD;
#pragma unroll
    for (int nt = 0; nt < 8; nt++) {
        const int c = nt * 8 + kc;
        *(float2*)&Cg0[c] = make_float2(tf32f(oacc[nt][0] * inv0),
                                        tf32f(oacc[nt][1] * inv0));
        *(float2*)&Cg1[c] = make_float2(tf32f(oacc[nt][2] * inv1),
                                        tf32f(oacc[nt][3] * inv1));
    }
}

// ---------------------------------------------------------------------------
// Launch: pre-round inputs -> QKV GEMMs (V transposed) -> attn -> out GEMM
// ---------------------------------------------------------------------------
extern "C" void kernel_launch(void* const* d_in, const int* in_sizes, int n_in,
                              void* d_out, int out_size)
{
    (void)in_sizes; (void)n_in; (void)out_size;
    const float* x  = (const float*)d_in[0];
    const float* Wq = (const float*)d_in[1];
    const float* bq = (const float*)d_in[2];
    const float* Wk = (const float*)d_in[3];
    const float* bk = (const float*)d_in[4];
    const float* Wv = (const float*)d_in[5];
    const float* bv = (const float*)d_in[6];
    const float* Wo = (const float*)d_in[7];
    const float* bo = (const float*)d_in[8];
    float* out = (float*)d_out;

    float *qp, *kp, *vp, *cp, *xr, *wqr, *wkr, *wvr, *wor;
    cudaGetSymbolAddress((void**)&qp, g_Q);
    cudaGetSymbolAddress((void**)&kp, g_K);
    cudaGetSymbolAddress((void**)&vp, g_V);
    cudaGetSymbolAddress((void**)&cp, g_C);
    cudaGetSymbolAddress((void**)&xr, g_Xr);
    cudaGetSymbolAddress((void**)&wqr, g_Wqr);
    cudaGetSymbolAddress((void**)&wkr, g_Wkr);
    cudaGetSymbolAddress((void**)&wvr, g_Wvr);
    cudaGetSymbolAddress((void**)&wor, g_Wor);

    cudaFuncSetAttribute(gemm_tf32<0>,
                         cudaFuncAttributeMaxDynamicSharedMemorySize,
                         GSM_BYTES);
    cudaFuncSetAttribute(gemm_tf32<1>,
                         cudaFuncAttributeMaxDynamicSharedMemorySize,
                         GSM_BYTES);
    cudaFuncSetAttribute(gemm_tf32<2>,
                         cudaFuncAttributeMaxDynamicSharedMemorySize,
                         GSM_BYTES);
    cudaFuncSetAttribute(attn_tc,
                         cudaFuncAttributeMaxDynamicSharedMemorySize,
                         ATT_SMEM_BYTES);

    // pre-round inputs to tf32 (idempotent, graph-capturable)
    const int xn4 = MROWS * DD / 4;
    const int wn4 = DD * DD / 4;
    round_tf32_kernel<<<xn4 / 256, 256>>>(x, xr, xn4);
    round_tf32_kernel<<<wn4 / 256, 256>>>(Wq, wqr, wn4);
    round_tf32_kernel<<<wn4 / 256, 256>>>(Wk, wkr, wn4);
    round_tf32_kernel<<<wn4 / 256, 256>>>(Wv, wvr, wn4);
    round_tf32_kernel<<<wn4 / 256, 256>>>(Wo, wor, wn4);

    const dim3 gblk(256);
    const dim3 ggrid(DD / 128, MROWS / 128);   // (8, 32)

    gemm_tf32<0><<<ggrid, gblk, GSM_BYTES>>>(xr, wqr, bq, qp);
    gemm_tf32<1><<<ggrid, gblk, GSM_BYTES>>>(xr, wkr, bk, kp);
    gemm_tf32<2><<<ggrid, gblk, GSM_BYTES>>>(xr, wvr, bv, vp);   // -> Vt

    attn_tc<<<dim3(SS / 128, HH, BB), 256, ATT_SMEM_BYTES>>>();

    gemm_tf32<0><<<ggrid, gblk, GSM_BYTES>>>(cp, wor, bo, out);
}